// round 16
// baseline (speedup 1.0000x reference)
#include <cuda_runtime.h>
#include <cuda_fp16.h>
#include <math.h>

#define NB 4
#define NT 512
#define ND 1024
#define NF 4096
#define NE 8
#define NHEAD 16
#define DH 64
#define NTOK (NB*NT)          // 2048
#define CAP 2048
#define NSLOT (NE*CAP)
typedef __half h16;

// ---- static scratch ----
__device__ float g_ln[NTOK*ND];                          // fp32 ln (gate input)
__device__ h16 g_lnh[NTOK*ND];
__device__ h16 g_qkvh[(size_t)NTOK*3*ND];
__device__ h16 g_ctxh[NTOK*ND];
__device__ h16 g_hidh[(size_t)NSLOT*NF];
__device__ h16 g_wqkvh[3*ND*ND];
__device__ h16 g_woh[ND*ND];
__device__ h16 g_w1h[(size_t)NE*ND*NF];
__device__ h16 g_w2h[(size_t)NE*NF*ND];
__device__ int   g_slot_token[NSLOT];
__device__ float g_slot_w[NSLOT];
__device__ int   g_count[NE];

__device__ __forceinline__ float gelu_tanh(float x){
    float x3 = x*x*x;
    return 0.5f*x*(1.0f + tanhf(0.7978845608028654f*(x + 0.044715f*x3)));
}
__device__ __forceinline__ unsigned round_pack(float x0, float x1){
    return ((unsigned)__half_as_ushort(__float2half_rn(x1))<<16)
         |  (unsigned)__half_as_ushort(__float2half_rn(x0));
}
__device__ __forceinline__ unsigned sptr(const void* p){
    return (unsigned)__cvta_generic_to_shared(p);
}
#define CPA16(dst,src)    asm volatile("cp.async.cg.shared.global [%0],[%1],16;\n"::"r"(dst),"l"(src):"memory")
#define CPA16Z(dst,src,z) asm volatile("cp.async.cg.shared.global [%0],[%1],16,%2;\n"::"r"(dst),"l"(src),"r"(z):"memory")
#define CPCOMMIT          asm volatile("cp.async.commit_group;\n":::"memory")
__device__ __forceinline__ void cp_wait0(){ asm volatile("cp.async.wait_group 0;\n":::"memory"); }
__device__ __forceinline__ void cp_wait1(){ asm volatile("cp.async.wait_group 1;\n":::"memory"); }

__device__ __forceinline__ void ldsm4(unsigned* r, unsigned a){
    asm volatile("ldmatrix.sync.aligned.m8n8.x4.shared.b16 {%0,%1,%2,%3},[%4];\n"
        :"=r"(r[0]),"=r"(r[1]),"=r"(r[2]),"=r"(r[3]):"r"(a));
}
__device__ __forceinline__ void ldsm4t(unsigned* r, unsigned a){
    asm volatile("ldmatrix.sync.aligned.m8n8.x4.trans.shared.b16 {%0,%1,%2,%3},[%4];\n"
        :"=r"(r[0]),"=r"(r[1]),"=r"(r[2]),"=r"(r[3]):"r"(a));
}
__device__ __forceinline__ void mma_f16(float* c, const unsigned* a, const unsigned* b){
    asm volatile("mma.sync.aligned.m16n8k16.row.col.f32.f16.f16.f32 "
        "{%0,%1,%2,%3}, {%4,%5,%6,%7}, {%8,%9}, {%0,%1,%2,%3};\n"
        : "+f"(c[0]),"+f"(c[1]),"+f"(c[2]),"+f"(c[3])
        : "r"(a[0]),"r"(a[1]),"r"(a[2]),"r"(a[3]), "r"(b[0]),"r"(b[1]));
}

// ================== fp16 GEMM core v5: 128x256 tile, 512 threads ==================
// BK=32, 3-stage cp.async, ldmatrix. 16 warps as 2m x 8n; warp tile 64x32
// (identical warp-level code to v3 — only staging and SB change).
// A: fp16 row-major [M,K] (pre-offset to block row, or rmap gather).
// B: fp16 k-major [K,N] (pre-offset by n0).
#define GEMM_SMEM (3*(128*40 + 32*264)*2)   // 81408 bytes

__device__ __forceinline__ void core_h(
    const h16* __restrict__ A, int lda, const int* __restrict__ rmap,
    const h16* __restrict__ Bm, int ldb, int K,
    float acc[4][4][4])
{
    constexpr int SA = 40;    // A smem row stride (halves)
    constexpr int SB = 264;   // B smem row stride (halves): 256 + 8 pad
    extern __shared__ h16 ds[];
    h16* As = ds;                   // 3 stages of 128*SA
    h16* Bs = ds + 3*128*SA;        // 3 stages of 32*SB

    const int tid=threadIdx.x, lane=tid&31, w=tid>>5;
    const int wm=(w&1)*64, wn=(w>>1)*32;
    const int lt=lane>>3, lr=lane&7;

    // A staging: row = tid>>2, one 16B chunk at halves (tid&3)*8
    const int ar = tid>>2, ak = (tid&3)*8;
    const h16* Ap;
    unsigned az = 16;
    if(rmap){ int tok=rmap[ar]; if(tok<0){ az=0; tok=0; } Ap = A + (size_t)tok*lda + ak; }
    else      Ap = A + (size_t)ar*lda + ak;
    const unsigned aoff = ar*SA + ak;

    // B staging: row(k) = tid>>4 (0..31), cols (tid&15)*16, two 16B chunks
    const int br = tid>>4, bc = (tid&15)*16;
    const h16* Bp = Bm + (size_t)br*ldb + bc;
    const unsigned boff = br*SB + bc;

    auto stage = [&](int s, int k0){
        h16* Ad = As + s*128*SA;
        h16* Bd = Bs + s*32*SB;
        if(rmap){ CPA16Z(sptr(&Ad[aoff]), Ap + k0, az); }
        else    { CPA16 (sptr(&Ad[aoff]), Ap + k0);     }
        CPA16(sptr(&Bd[boff]),   Bp + (size_t)k0*ldb);
        CPA16(sptr(&Bd[boff+8]), Bp + (size_t)k0*ldb + 8);
    };

    auto compute = [&](int s){
        h16* Ad = As + s*128*SA;
        h16* Bd = Bs + s*32*SB;
        #pragma unroll
        for(int kk=0;kk<32;kk+=16){
            unsigned aR[4][4], bR[4][2];
            #pragma unroll
            for(int i=0;i<4;i++){
                unsigned off = (unsigned)((wm + i*16 + (lt&1)*8 + lr)*SA + kk + (lt>>1)*8);
                ldsm4(aR[i], sptr(Ad + off));
            }
            #pragma unroll
            for(int jp=0;jp<2;jp++){
                unsigned off = (unsigned)((kk + (lt&1)*8 + lr)*SB + wn + jp*16 + (lt>>1)*8);
                unsigned r[4];
                ldsm4t(r, sptr(Bd + off));
                bR[jp*2][0]=r[0];   bR[jp*2][1]=r[1];
                bR[jp*2+1][0]=r[2]; bR[jp*2+1][1]=r[3];
            }
            #pragma unroll
            for(int i=0;i<4;i++)
                #pragma unroll
                for(int j=0;j<4;j++)
                    mma_f16(acc[i][j], aR[i], bR[j]);
        }
    };

    const int KT = K/32;
    stage(0, 0);  CPCOMMIT;
    stage(1, 32); CPCOMMIT;
    for(int s=0;s<KT;s++){
        if(s+2<KT) cp_wait1(); else cp_wait0();
        __syncthreads();
        if(s+2<KT){ stage((s+2)%3, (s+2)*32); CPCOMMIT; }
        compute(s%3);
    }
}

// ================== fused flash attention (unchanged) ==================
#define SQ 72
#define FLASH_SMEM (5*128*SQ*2)   // 92160 bytes

__global__ __launch_bounds__(256,2) void flash_attn(){
    extern __shared__ h16 fs[];
    h16* Qs = fs;
    h16* Ks = fs + 128*SQ;
    h16* Vs = fs + 3*128*SQ;
    const int bh = blockIdx.y, b = bh>>4, h = bh&15;
    const int m0 = blockIdx.x*128;
    const size_t qb = (size_t)b*NT*3*ND;
    const h16* Qg = g_qkvh + qb + h*DH;
    const h16* Kg = g_qkvh + qb + ND + h*DH;
    const h16* Vg = g_qkvh + qb + 2*ND + h*DH;
    const int tid=threadIdx.x, lane=tid&31, w=tid>>5;
    const int g=lane>>2, q=lane&3;

    int srow[4], scc[4];
    #pragma unroll
    for(int i=0;i<4;i++){ int c=tid*4+i; srow[i]=c>>3; scc[i]=(c&7)*8; }

    #pragma unroll
    for(int i=0;i<4;i++){
        CPA16(sptr(&Qs[srow[i]*SQ+scc[i]]), Qg + (size_t)(m0+srow[i])*3*ND + scc[i]);
        CPA16(sptr(&Ks[srow[i]*SQ+scc[i]]), Kg + (size_t)srow[i]*3*ND + scc[i]);
        CPA16(sptr(&Vs[srow[i]*SQ+scc[i]]), Vg + (size_t)srow[i]*3*ND + scc[i]);
    }
    CPCOMMIT;

    float mrow[2] = {-1e30f,-1e30f};
    float lrow[2] = {0.f,0.f};
    float O[8][4] = {};

    for(int jb=0;jb<4;jb++){
        const int buf = jb&1;
        if(jb<3){
            const int nb=(jb+1)&1;
            #pragma unroll
            for(int i=0;i<4;i++){
                CPA16(sptr(&Ks[nb*128*SQ + srow[i]*SQ+scc[i]]), Kg + (size_t)((jb+1)*128+srow[i])*3*ND + scc[i]);
                CPA16(sptr(&Vs[nb*128*SQ + srow[i]*SQ+scc[i]]), Vg + (size_t)((jb+1)*128+srow[i])*3*ND + scc[i]);
            }
            CPCOMMIT; cp_wait1();
        } else cp_wait0();
        __syncthreads();
        const h16* Kb = Ks + buf*128*SQ;
        const h16* Vb = Vs + buf*128*SQ;

        #pragma unroll
        for(int hh=0; hh<2; hh++){
            float s[8][4] = {};
            #pragma unroll
            for(int kk=0;kk<4;kk++){
                unsigned a[4];
                int ab = (w*16+g)*SQ + kk*16 + q*2;
                a[0]=*(const unsigned*)&Qs[ab];   a[1]=*(const unsigned*)&Qs[ab+8*SQ];
                a[2]=*(const unsigned*)&Qs[ab+8]; a[3]=*(const unsigned*)&Qs[ab+8*SQ+8];
                #pragma unroll
                for(int j16=0;j16<8;j16++){
                    unsigned bfr[2];
                    int bb = (hh*64 + j16*8 + g)*SQ + kk*16 + q*2;
                    bfr[0]=*(const unsigned*)&Kb[bb]; bfr[1]=*(const unsigned*)&Kb[bb+8];
                    mma_f16(s[j16], a, bfr);
                }
            }
            float mx0=-1e30f, mx1=-1e30f;
            #pragma unroll
            for(int j16=0;j16<8;j16++){
                s[j16][0]*=0.125f; s[j16][1]*=0.125f; s[j16][2]*=0.125f; s[j16][3]*=0.125f;
                mx0 = fmaxf(mx0, fmaxf(s[j16][0], s[j16][1]));
                mx1 = fmaxf(mx1, fmaxf(s[j16][2], s[j16][3]));
            }
            mx0 = fmaxf(mx0, __shfl_xor_sync(0xffffffffu, mx0, 1));
            mx0 = fmaxf(mx0, __shfl_xor_sync(0xffffffffu, mx0, 2));
            mx1 = fmaxf(mx1, __shfl_xor_sync(0xffffffffu, mx1, 1));
            mx1 = fmaxf(mx1, __shfl_xor_sync(0xffffffffu, mx1, 2));
            float mn0 = fmaxf(mrow[0], mx0), mn1 = fmaxf(mrow[1], mx1);
            float sc0 = __expf(mrow[0]-mn0), sc1 = __expf(mrow[1]-mn1);
            float rs0=0.f, rs1=0.f;
            #pragma unroll
            for(int j16=0;j16<8;j16++){
                s[j16][0]=__expf(s[j16][0]-mn0); s[j16][1]=__expf(s[j16][1]-mn0);
                s[j16][2]=__expf(s[j16][2]-mn1); s[j16][3]=__expf(s[j16][3]-mn1);
                rs0 += s[j16][0]+s[j16][1]; rs1 += s[j16][2]+s[j16][3];
            }
            rs0 += __shfl_xor_sync(0xffffffffu, rs0, 1);
            rs0 += __shfl_xor_sync(0xffffffffu, rs0, 2);
            rs1 += __shfl_xor_sync(0xffffffffu, rs1, 1);
            rs1 += __shfl_xor_sync(0xffffffffu, rs1, 2);
            lrow[0] = lrow[0]*sc0 + rs0; lrow[1] = lrow[1]*sc1 + rs1;
            mrow[0]=mn0; mrow[1]=mn1;
            #pragma unroll
            for(int j2=0;j2<8;j2++){ O[j2][0]*=sc0; O[j2][1]*=sc0; O[j2][2]*=sc1; O[j2][3]*=sc1; }
            #pragma unroll
            for(int kk2=0;kk2<4;kk2++){
                unsigned a[4];
                a[0]=round_pack(s[2*kk2][0],  s[2*kk2][1]);
                a[1]=round_pack(s[2*kk2][2],  s[2*kk2][3]);
                a[2]=round_pack(s[2*kk2+1][0],s[2*kk2+1][1]);
                a[3]=round_pack(s[2*kk2+1][2],s[2*kk2+1][3]);
                int t0 = hh*64 + kk2*16 + q*2;
                #pragma unroll
                for(int j2=0;j2<8;j2++){
                    int n = j2*8 + g;
                    const unsigned short* vp = (const unsigned short*)&Vb[t0*SQ + n];
                    unsigned bfr[2];
                    bfr[0] = (unsigned)vp[0]    | ((unsigned)vp[SQ]  <<16);
                    bfr[1] = (unsigned)vp[8*SQ] | ((unsigned)vp[9*SQ]<<16);
                    mma_f16(O[j2], a, bfr);
                }
            }
        }
        __syncthreads();
    }
    float inv0 = 1.f/lrow[0], inv1 = 1.f/lrow[1];
    int row0 = m0 + w*16 + g;
    size_t ob0 = (size_t)(b*NT + row0)*ND + h*DH;
    size_t ob1 = (size_t)(b*NT + row0 + 8)*ND + h*DH;
    #pragma unroll
    for(int j2=0;j2<8;j2++){
        int col = j2*8 + q*2;
        *(unsigned*)&g_ctxh[ob0+col] = round_pack(O[j2][0]*inv0, O[j2][1]*inv0);
        *(unsigned*)&g_ctxh[ob1+col] = round_pack(O[j2][2]*inv1, O[j2][3]*inv1);
    }
}

// ================== GEMM kernels (512 threads, 128x256 tiles) ==================

__global__ __launch_bounds__(512,2) void tc_qkv(const float* __restrict__ bias){
    const int m0 = blockIdx.y*128, n0 = blockIdx.x*256;
    float acc[4][4][4] = {};
    core_h(g_lnh + (size_t)m0*ND, ND, nullptr, g_wqkvh + n0, 3*ND, ND, acc);
    const int lane = threadIdx.x&31, w = threadIdx.x>>5;
    const int wm = (w&1)*64, wn = (w>>1)*32;
    const int g = lane>>2, q = lane&3;
    #pragma unroll
    for(int i=0;i<4;i++)
        #pragma unroll
        for(int j=0;j<4;j++)
            #pragma unroll
            for(int hh=0;hh<2;hh++){
                int row = m0 + wm + i*16 + g + hh*8;
                int col = n0 + wn + j*8 + q*2;
                *(unsigned*)&g_qkvh[(size_t)row*3*ND+col] =
                    round_pack(acc[i][j][hh*2] + bias[col], acc[i][j][hh*2+1] + bias[col+1]);
            }
}

__global__ __launch_bounds__(512,2) void tc_o(
    const float* __restrict__ bias, const float* __restrict__ res, float* __restrict__ out){
    const int m0 = blockIdx.y*128, n0 = blockIdx.x*256;
    float acc[4][4][4] = {};
    core_h(g_ctxh + (size_t)m0*ND, ND, nullptr, g_woh + n0, ND, ND, acc);
    const int lane = threadIdx.x&31, w = threadIdx.x>>5;
    const int wm = (w&1)*64, wn = (w>>1)*32;
    const int g = lane>>2, q = lane&3;
    #pragma unroll
    for(int i=0;i<4;i++)
        #pragma unroll
        for(int j=0;j<4;j++)
            #pragma unroll
            for(int hh=0;hh<2;hh++){
                int row = m0 + wm + i*16 + g + hh*8;
                int col = n0 + wn + j*8 + q*2;
                float2 r = *(const float2*)&res[(size_t)row*ND+col];
                float2 o;
                o.x = acc[i][j][hh*2]   + bias[col]   + r.x;
                o.y = acc[i][j][hh*2+1] + bias[col+1] + r.y;
                *(float2*)&out[(size_t)row*ND+col] = o;
            }
}

__global__ __launch_bounds__(512,2) void tc_moe_gemm1(const float* __restrict__ b1){
    const int e = blockIdx.y >> 4;
    const int rt = blockIdx.y & 15;
    if(rt*128 >= g_count[e]) return;
    const int m0 = rt*128, n0 = blockIdx.x*256;
    float acc[4][4][4] = {};
    core_h(g_lnh, ND, &g_slot_token[e*CAP + m0], g_w1h + (size_t)e*ND*NF + n0, NF, ND, acc);
    const int lane = threadIdx.x&31, w = threadIdx.x>>5;
    const int wm = (w&1)*64, wn = (w>>1)*32;
    const int g = lane>>2, q = lane&3;
    #pragma unroll
    for(int i=0;i<4;i++)
        #pragma unroll
        for(int j=0;j<4;j++)
            #pragma unroll
            for(int hh=0;hh<2;hh++){
                int sl  = m0 + wm + i*16 + g + hh*8;
                int col = n0 + wn + j*8 + q*2;
                float v0 = gelu_tanh(acc[i][j][hh*2]   + b1[e*NF + col]);
                float v1 = gelu_tanh(acc[i][j][hh*2+1] + b1[e*NF + col+1]);
                *(unsigned*)&g_hidh[(size_t)(e*CAP+sl)*NF + col] = round_pack(v0, v1);
            }
}

__global__ __launch_bounds__(512,2) void tc_moe_gemm2(const float* __restrict__ b2, float* __restrict__ out){
    const int e = blockIdx.y >> 4;
    const int rt = blockIdx.y & 15;
    const int cnt = g_count[e];
    if(rt*128 >= cnt) return;
    const int m0 = rt*128, n0 = blockIdx.x*256;
    float acc[4][4][4] = {};
    core_h(g_hidh + (size_t)(e*CAP + m0)*NF, NF, nullptr, g_w2h + (size_t)e*NF*ND + n0, ND, NF, acc);
    const int lane = threadIdx.x&31, w = threadIdx.x>>5;
    const int wm = (w&1)*64, wn = (w>>1)*32;
    const int g = lane>>2, q = lane&3;
    #pragma unroll
    for(int i=0;i<4;i++)
        #pragma unroll
        for(int j=0;j<4;j++)
            #pragma unroll
            for(int hh=0;hh<2;hh++){
                int sl = m0 + wm + i*16 + g + hh*8;
                if(sl < cnt){
                    int tok = g_slot_token[e*CAP + sl];
                    float ws = g_slot_w[e*CAP + sl];
                    int col = n0 + wn + j*8 + q*2;
                    atomicAdd(&out[(size_t)tok*ND + col],   ws*(acc[i][j][hh*2]   + b2[e*ND + col]));
                    atomicAdd(&out[(size_t)tok*ND + col+1], ws*(acc[i][j][hh*2+1] + b2[e*ND + col+1]));
                }
            }
}

// ================== auxiliary kernels ==================

__global__ void conv_h_kernel(const float* __restrict__ src, h16* __restrict__ dst){
    size_t i = ((size_t)blockIdx.x*256 + threadIdx.x)*8;
    float4 a = *(const float4*)(src + i);
    float4 b = *(const float4*)(src + i + 4);
    *(uint4*)&dst[i] = make_uint4(round_pack(a.x,a.y), round_pack(a.z,a.w),
                                  round_pack(b.x,b.y), round_pack(b.z,b.w));
}

__global__ void ln_kernel(const float* __restrict__ x,
                          const float* __restrict__ w,
                          const float* __restrict__ b,
                          float* __restrict__ y, h16* __restrict__ yh)
{
    int row = blockIdx.x;
    int t = threadIdx.x;
    float4 v = *(const float4*)(x + (size_t)row*ND + t*4);
    float s = v.x+v.y+v.z+v.w;
    __shared__ float red[256];
    red[t] = s; __syncthreads();
    for(int o=128;o>0;o>>=1){ if(t<o) red[t]+=red[t+o]; __syncthreads(); }
    float mu = red[0]*(1.0f/ND);
    __syncthreads();
    float d0=v.x-mu, d1=v.y-mu, d2=v.z-mu, d3=v.w-mu;
    red[t] = d0*d0+d1*d1+d2*d2+d3*d3; __syncthreads();
    for(int o=128;o>0;o>>=1){ if(t<o) red[t]+=red[t+o]; __syncthreads(); }
    float rstd = rsqrtf(red[0]*(1.0f/ND) + 1e-5f);
    float4 wv = *(const float4*)(w + t*4);
    float4 bv = *(const float4*)(b + t*4);
    float4 o;
    o.x = d0*rstd*wv.x + bv.x;
    o.y = d1*rstd*wv.y + bv.y;
    o.z = d2*rstd*wv.z + bv.z;
    o.w = d3*rstd*wv.w + bv.w;
    *(float4*)(y + (size_t)row*ND + t*4) = o;
    *(uint2*)&yh[(size_t)row*ND + t*4] = make_uint2(round_pack(o.x,o.y), round_pack(o.z,o.w));
}

__global__ void moe_reset_kernel()
{
    int i = blockIdx.x*256 + threadIdx.x;
    if(i < NSLOT) g_slot_token[i] = -1;
    if(i < NE) g_count[i] = 0;
}

__global__ void gate_kernel(const float* __restrict__ wg)
{
    int token = blockIdx.x*8 + (threadIdx.x>>5);
    int lane = threadIdx.x & 31;
    const float* t = g_ln + (size_t)token*ND;
    float acc[NE] = {};
    for(int d=lane; d<ND; d+=32){
        float td = t[d];
        const float* w = wg + d*NE;
        #pragma unroll
        for(int e=0;e<NE;e++) acc[e] += td*w[e];
    }
    #pragma unroll
    for(int e=0;e<NE;e++)
        #pragma unroll
        for(int o=16;o>0;o>>=1) acc[e] += __shfl_xor_sync(0xffffffffu, acc[e], o);
    if(lane==0){
        float mx = -1e30f;
        #pragma unroll
        for(int e=0;e<NE;e++) mx = fmaxf(mx, acc[e]);
        float p[NE], s=0.f;
        #pragma unroll
        for(int e=0;e<NE;e++){ p[e] = expf(acc[e]-mx); s += p[e]; }
        float inv = 1.0f/s;
        #pragma unroll
        for(int e=0;e<NE;e++) p[e] *= inv;
        int e0 = 0;
        #pragma unroll
        for(int e=1;e<NE;e++) if(p[e] > p[e0]) e0 = e;
        int e1 = (e0==0) ? 1 : 0;
        #pragma unroll
        for(int e=0;e<NE;e++) if(e!=e0 && p[e] > p[e1]) e1 = e;
        float w0 = p[e0], w1 = p[e1];
        float rn = 1.0f/(w0+w1);
        w0 *= rn; w1 *= rn;
        int p0 = atomicAdd(&g_count[e0], 1);
        g_slot_token[e0*CAP + p0] = token; g_slot_w[e0*CAP + p0] = w0;
        int p1 = atomicAdd(&g_count[e1], 1);
        g_slot_token[e1*CAP + p1] = token; g_slot_w[e1*CAP + p1] = w1;
    }
}

// ================== launch ==================
extern "C" void kernel_launch(void* const* d_in, const int* in_sizes, int n_in,
                              void* d_out, int out_size)
{
    const float* x    = (const float*)d_in[0];
    const float* ln1w = (const float*)d_in[1];
    const float* ln1b = (const float*)d_in[2];
    const float* ln2w = (const float*)d_in[3];
    const float* ln2b = (const float*)d_in[4];
    const float* wqkv = (const float*)d_in[5];
    const float* bqkv = (const float*)d_in[6];
    const float* wo   = (const float*)d_in[7];
    const float* bo   = (const float*)d_in[8];
    const float* wg   = (const float*)d_in[9];
    const float* w1   = (const float*)d_in[10];
    const float* b1   = (const float*)d_in[11];
    const float* w2   = (const float*)d_in[12];
    const float* b2   = (const float*)d_in[13];
    float* out = (float*)d_out;

    float *p_ln;
    h16 *p_lnh, *p_wqkvh, *p_woh, *p_w1h, *p_w2h;
    cudaGetSymbolAddress((void**)&p_ln,    g_ln);
    cudaGetSymbolAddress((void**)&p_lnh,   g_lnh);
    cudaGetSymbolAddress((void**)&p_wqkvh, g_wqkvh);
    cudaGetSymbolAddress((void**)&p_woh,   g_woh);
    cudaGetSymbolAddress((void**)&p_w1h,   g_w1h);
    cudaGetSymbolAddress((void**)&p_w2h,   g_w2h);

    cudaFuncSetAttribute(flash_attn,   cudaFuncAttributeMaxDynamicSharedMemorySize, FLASH_SMEM);
    cudaFuncSetAttribute(tc_qkv,       cudaFuncAttributeMaxDynamicSharedMemorySize, GEMM_SMEM);
    cudaFuncSetAttribute(tc_o,         cudaFuncAttributeMaxDynamicSharedMemorySize, GEMM_SMEM);
    cudaFuncSetAttribute(tc_moe_gemm1, cudaFuncAttributeMaxDynamicSharedMemorySize, GEMM_SMEM);
    cudaFuncSetAttribute(tc_moe_gemm2, cudaFuncAttributeMaxDynamicSharedMemorySize, GEMM_SMEM);

    // weight conversions on side stream, ordered by first use
    cudaStream_t s2;
    cudaEvent_t evFork, evQ, evWo, evW12;
    cudaStreamCreateWithFlags(&s2, cudaStreamNonBlocking);
    cudaEventCreateWithFlags(&evFork, cudaEventDisableTiming);
    cudaEventCreateWithFlags(&evQ,    cudaEventDisableTiming);
    cudaEventCreateWithFlags(&evWo,   cudaEventDisableTiming);
    cudaEventCreateWithFlags(&evW12,  cudaEventDisableTiming);

    cudaEventRecord(evFork, 0);
    cudaStreamWaitEvent(s2, evFork, 0);
    conv_h_kernel<<<3*ND*ND/2048, 256, 0, s2>>>(wqkv, p_wqkvh);
    cudaEventRecord(evQ, s2);
    conv_h_kernel<<<ND*ND/2048,   256, 0, s2>>>(wo, p_woh);
    cudaEventRecord(evWo, s2);
    conv_h_kernel<<<NE*ND*NF/2048,256, 0, s2>>>(w1, p_w1h);
    conv_h_kernel<<<NE*NF*ND/2048,256, 0, s2>>>(w2, p_w2h);
    cudaEventRecord(evW12, s2);

    // main stream
    ln_kernel<<<NTOK, 256>>>(x, ln1w, ln1b, p_ln, p_lnh);
    cudaStreamWaitEvent(0, evQ, 0);
    tc_qkv<<<dim3(3*ND/256, NTOK/128), 512, GEMM_SMEM>>>(bqkv);
    flash_attn<<<dim3(NT/128, NB*NHEAD), 256, FLASH_SMEM>>>();
    cudaStreamWaitEvent(0, evWo, 0);
    tc_o<<<dim3(ND/256, NTOK/128), 512, GEMM_SMEM>>>(bo, x, out);
    ln_kernel<<<NTOK, 256>>>(out, ln2w, ln2b, p_ln, p_lnh);
    moe_reset_kernel<<<NSLOT/256, 256>>>();
    gate_kernel<<<NTOK/8, 256>>>(wg);
    cudaStreamWaitEvent(0, evW12, 0);
    tc_moe_gemm1<<<dim3(NF/256, NE*16), 512, GEMM_SMEM>>>(b1);
    tc_moe_gemm2<<<dim3(ND/256, NE*16), 512, GEMM_SMEM>>>(b2, out);

    cudaStreamDestroy(s2);
    cudaEventDestroy(evFork);
    cudaEventDestroy(evQ);
    cudaEventDestroy(evWo);
    cudaEventDestroy(evW12);
}

// round 17
// speedup vs baseline: 3.7602x; 3.7602x over previous
#include <cuda_runtime.h>
#include <cuda_fp16.h>
#include <math.h>

#define NB 4
#define NT 512
#define ND 1024
#define NF 4096
#define NE 8
#define NHEAD 16
#define DH 64
#define NTOK (NB*NT)          // 2048
#define CAP 2048
#define NSLOT (NE*CAP)
typedef __half h16;

// ---- static scratch ----
__device__ float g_ln[NTOK*ND];                          // fp32 ln (gate input)
__device__ h16 g_lnh[NTOK*ND];
__device__ h16 g_qkvh[(size_t)NTOK*3*ND];
__device__ h16 g_ctxh[NTOK*ND];
__device__ h16 g_hidh[(size_t)NSLOT*NF];
__device__ h16 g_wqkvh[3*ND*ND];
__device__ h16 g_woh[ND*ND];
__device__ h16 g_w1h[(size_t)NE*ND*NF];
__device__ h16 g_w2h[(size_t)NE*NF*ND];
__device__ int   g_slot_token[NSLOT];
__device__ float g_slot_w[NSLOT];
__device__ int   g_count[NE];

__device__ __forceinline__ float gelu_tanh(float x){
    float x3 = x*x*x;
    return 0.5f*x*(1.0f + tanhf(0.7978845608028654f*(x + 0.044715f*x3)));
}
__device__ __forceinline__ unsigned round_pack(float x0, float x1){
    return ((unsigned)__half_as_ushort(__float2half_rn(x1))<<16)
         |  (unsigned)__half_as_ushort(__float2half_rn(x0));
}
__device__ __forceinline__ unsigned sptr(const void* p){
    return (unsigned)__cvta_generic_to_shared(p);
}
#define CPA16(dst,src)    asm volatile("cp.async.cg.shared.global [%0],[%1],16;\n"::"r"(dst),"l"(src):"memory")
#define CPA16Z(dst,src,z) asm volatile("cp.async.cg.shared.global [%0],[%1],16,%2;\n"::"r"(dst),"l"(src),"r"(z):"memory")
#define CPCOMMIT          asm volatile("cp.async.commit_group;\n":::"memory")
__device__ __forceinline__ void cp_wait0(){ asm volatile("cp.async.wait_group 0;\n":::"memory"); }
__device__ __forceinline__ void cp_wait1(){ asm volatile("cp.async.wait_group 1;\n":::"memory"); }

__device__ __forceinline__ void ldsm4(unsigned* r, unsigned a){
    asm volatile("ldmatrix.sync.aligned.m8n8.x4.shared.b16 {%0,%1,%2,%3},[%4];\n"
        :"=r"(r[0]),"=r"(r[1]),"=r"(r[2]),"=r"(r[3]):"r"(a));
}
__device__ __forceinline__ void ldsm4t(unsigned* r, unsigned a){
    asm volatile("ldmatrix.sync.aligned.m8n8.x4.trans.shared.b16 {%0,%1,%2,%3},[%4];\n"
        :"=r"(r[0]),"=r"(r[1]),"=r"(r[2]),"=r"(r[3]):"r"(a));
}
__device__ __forceinline__ void mma_f16(float* c, const unsigned* a, const unsigned* b){
    asm volatile("mma.sync.aligned.m16n8k16.row.col.f32.f16.f16.f32 "
        "{%0,%1,%2,%3}, {%4,%5,%6,%7}, {%8,%9}, {%0,%1,%2,%3};\n"
        : "+f"(c[0]),"+f"(c[1]),"+f"(c[2]),"+f"(c[3])
        : "r"(a[0]),"r"(a[1]),"r"(a[2]),"r"(a[3]), "r"(b[0]),"r"(b[1]));
}

// ================== fp16 GEMM core v3: ldmatrix + 3-stage cp.async, BK=32 ==================
// 128x128 tile, 256 threads (8 warps, 2m x 4n, warp tile 64x32).
// A: fp16 row-major [M,K] (pre-offset to block row, or rmap gather).
// B: fp16 k-major [K,N] (pre-offset by n0).
#define GEMM_SMEM (3*(128*40 + 32*136)*2)   // 56832 bytes

__device__ __forceinline__ void core_h(
    const h16* __restrict__ A, int lda, const int* __restrict__ rmap,
    const h16* __restrict__ Bm, int ldb, int K,
    float acc[4][4][4])
{
    constexpr int SA = 40;    // A smem row stride (halves)
    constexpr int SB = 136;   // B smem row stride (halves)
    extern __shared__ h16 ds[];
    h16* As = ds;                   // 3 stages of 128*SA
    h16* Bs = ds + 3*128*SA;        // 3 stages of 32*SB

    const int tid=threadIdx.x, lane=tid&31, w=tid>>5;
    const int wm=(w&1)*64, wn=(w>>1)*32;
    const int lt=lane>>3, lr=lane&7;

    // A staging: row = tid>>1, two 16B chunks at halves (tid&1)*16, +8
    const int ar = tid>>1, ak = (tid&1)*16;
    const h16* Ap;
    unsigned az = 16;
    if(rmap){ int tok=rmap[ar]; if(tok<0){ az=0; tok=0; } Ap = A + (size_t)tok*lda + ak; }
    else      Ap = A + (size_t)ar*lda + ak;
    const unsigned aoff = ar*SA + ak;

    // B staging: row(k) = tid>>3, col = (tid&7)*16, two chunks
    const int br = tid>>3, bc = (tid&7)*16;
    const h16* Bp = Bm + (size_t)br*ldb + bc;
    const unsigned boff = br*SB + bc;

    auto stage = [&](int s, int k0){
        h16* Ad = As + s*128*SA;
        h16* Bd = Bs + s*32*SB;
        if(rmap){
            CPA16Z(sptr(&Ad[aoff]),   Ap + k0,     az);
            CPA16Z(sptr(&Ad[aoff+8]), Ap + k0 + 8, az);
        } else {
            CPA16(sptr(&Ad[aoff]),   Ap + k0);
            CPA16(sptr(&Ad[aoff+8]), Ap + k0 + 8);
        }
        CPA16(sptr(&Bd[boff]),   Bp + (size_t)k0*ldb);
        CPA16(sptr(&Bd[boff+8]), Bp + (size_t)k0*ldb + 8);
    };

    auto compute = [&](int s){
        h16* Ad = As + s*128*SA;
        h16* Bd = Bs + s*32*SB;
        #pragma unroll
        for(int kk=0;kk<32;kk+=16){
            unsigned aR[4][4], bR[4][2];
            #pragma unroll
            for(int i=0;i<4;i++){
                unsigned off = (unsigned)((wm + i*16 + (lt&1)*8 + lr)*SA + kk + (lt>>1)*8);
                ldsm4(aR[i], sptr(Ad + off));
            }
            #pragma unroll
            for(int jp=0;jp<2;jp++){
                unsigned off = (unsigned)((kk + (lt&1)*8 + lr)*SB + wn + jp*16 + (lt>>1)*8);
                unsigned r[4];
                ldsm4t(r, sptr(Bd + off));
                bR[jp*2][0]=r[0];   bR[jp*2][1]=r[1];
                bR[jp*2+1][0]=r[2]; bR[jp*2+1][1]=r[3];
            }
            #pragma unroll
            for(int i=0;i<4;i++)
                #pragma unroll
                for(int j=0;j<4;j++)
                    mma_f16(acc[i][j], aR[i], bR[j]);
        }
    };

    const int KT = K/32;
    stage(0, 0);  CPCOMMIT;
    stage(1, 32); CPCOMMIT;
    for(int s=0;s<KT;s++){
        if(s+2<KT) cp_wait1(); else cp_wait0();
        __syncthreads();
        if(s+2<KT){ stage((s+2)%3, (s+2)*32); CPCOMMIT; }
        compute(s%3);
    }
}

// ================== fused flash attention ==================
#define SQ 72
#define FLASH_SMEM (5*128*SQ*2)   // 92160 bytes

__global__ __launch_bounds__(256,2) void flash_attn(){
    extern __shared__ h16 fs[];
    h16* Qs = fs;
    h16* Ks = fs + 128*SQ;
    h16* Vs = fs + 3*128*SQ;
    const int bh = blockIdx.y, b = bh>>4, h = bh&15;
    const int m0 = blockIdx.x*128;
    const size_t qb = (size_t)b*NT*3*ND;
    const h16* Qg = g_qkvh + qb + h*DH;
    const h16* Kg = g_qkvh + qb + ND + h*DH;
    const h16* Vg = g_qkvh + qb + 2*ND + h*DH;
    const int tid=threadIdx.x, lane=tid&31, w=tid>>5;
    const int g=lane>>2, q=lane&3;

    int srow[4], scc[4];
    #pragma unroll
    for(int i=0;i<4;i++){ int c=tid*4+i; srow[i]=c>>3; scc[i]=(c&7)*8; }

    #pragma unroll
    for(int i=0;i<4;i++){
        CPA16(sptr(&Qs[srow[i]*SQ+scc[i]]), Qg + (size_t)(m0+srow[i])*3*ND + scc[i]);
        CPA16(sptr(&Ks[srow[i]*SQ+scc[i]]), Kg + (size_t)srow[i]*3*ND + scc[i]);
        CPA16(sptr(&Vs[srow[i]*SQ+scc[i]]), Vg + (size_t)srow[i]*3*ND + scc[i]);
    }
    CPCOMMIT;

    float mrow[2] = {-1e30f,-1e30f};
    float lrow[2] = {0.f,0.f};
    float O[8][4] = {};

    for(int jb=0;jb<4;jb++){
        const int buf = jb&1;
        if(jb<3){
            const int nb=(jb+1)&1;
            #pragma unroll
            for(int i=0;i<4;i++){
                CPA16(sptr(&Ks[nb*128*SQ + srow[i]*SQ+scc[i]]), Kg + (size_t)((jb+1)*128+srow[i])*3*ND + scc[i]);
                CPA16(sptr(&Vs[nb*128*SQ + srow[i]*SQ+scc[i]]), Vg + (size_t)((jb+1)*128+srow[i])*3*ND + scc[i]);
            }
            CPCOMMIT; cp_wait1();
        } else cp_wait0();
        __syncthreads();
        const h16* Kb = Ks + buf*128*SQ;
        const h16* Vb = Vs + buf*128*SQ;

        #pragma unroll
        for(int hh=0; hh<2; hh++){
            float s[8][4] = {};
            #pragma unroll
            for(int kk=0;kk<4;kk++){
                unsigned a[4];
                int ab = (w*16+g)*SQ + kk*16 + q*2;
                a[0]=*(const unsigned*)&Qs[ab];   a[1]=*(const unsigned*)&Qs[ab+8*SQ];
                a[2]=*(const unsigned*)&Qs[ab+8]; a[3]=*(const unsigned*)&Qs[ab+8*SQ+8];
                #pragma unroll
                for(int j16=0;j16<8;j16++){
                    unsigned bfr[2];
                    int bb = (hh*64 + j16*8 + g)*SQ + kk*16 + q*2;
                    bfr[0]=*(const unsigned*)&Kb[bb]; bfr[1]=*(const unsigned*)&Kb[bb+8];
                    mma_f16(s[j16], a, bfr);
                }
            }
            float mx0=-1e30f, mx1=-1e30f;
            #pragma unroll
            for(int j16=0;j16<8;j16++){
                s[j16][0]*=0.125f; s[j16][1]*=0.125f; s[j16][2]*=0.125f; s[j16][3]*=0.125f;
                mx0 = fmaxf(mx0, fmaxf(s[j16][0], s[j16][1]));
                mx1 = fmaxf(mx1, fmaxf(s[j16][2], s[j16][3]));
            }
            mx0 = fmaxf(mx0, __shfl_xor_sync(0xffffffffu, mx0, 1));
            mx0 = fmaxf(mx0, __shfl_xor_sync(0xffffffffu, mx0, 2));
            mx1 = fmaxf(mx1, __shfl_xor_sync(0xffffffffu, mx1, 1));
            mx1 = fmaxf(mx1, __shfl_xor_sync(0xffffffffu, mx1, 2));
            float mn0 = fmaxf(mrow[0], mx0), mn1 = fmaxf(mrow[1], mx1);
            float sc0 = __expf(mrow[0]-mn0), sc1 = __expf(mrow[1]-mn1);
            float rs0=0.f, rs1=0.f;
            #pragma unroll
            for(int j16=0;j16<8;j16++){
                s[j16][0]=__expf(s[j16][0]-mn0); s[j16][1]=__expf(s[j16][1]-mn0);
                s[j16][2]=__expf(s[j16][2]-mn1); s[j16][3]=__expf(s[j16][3]-mn1);
                rs0 += s[j16][0]+s[j16][1]; rs1 += s[j16][2]+s[j16][3];
            }
            rs0 += __shfl_xor_sync(0xffffffffu, rs0, 1);
            rs0 += __shfl_xor_sync(0xffffffffu, rs0, 2);
            rs1 += __shfl_xor_sync(0xffffffffu, rs1, 1);
            rs1 += __shfl_xor_sync(0xffffffffu, rs1, 2);
            lrow[0] = lrow[0]*sc0 + rs0; lrow[1] = lrow[1]*sc1 + rs1;
            mrow[0]=mn0; mrow[1]=mn1;
            #pragma unroll
            for(int j2=0;j2<8;j2++){ O[j2][0]*=sc0; O[j2][1]*=sc0; O[j2][2]*=sc1; O[j2][3]*=sc1; }
            #pragma unroll
            for(int kk2=0;kk2<4;kk2++){
                unsigned a[4];
                a[0]=round_pack(s[2*kk2][0],  s[2*kk2][1]);
                a[1]=round_pack(s[2*kk2][2],  s[2*kk2][3]);
                a[2]=round_pack(s[2*kk2+1][0],s[2*kk2+1][1]);
                a[3]=round_pack(s[2*kk2+1][2],s[2*kk2+1][3]);
                int t0 = hh*64 + kk2*16 + q*2;
                #pragma unroll
                for(int j2=0;j2<8;j2++){
                    int n = j2*8 + g;
                    const unsigned short* vp = (const unsigned short*)&Vb[t0*SQ + n];
                    unsigned bfr[2];
                    bfr[0] = (unsigned)vp[0]    | ((unsigned)vp[SQ]  <<16);
                    bfr[1] = (unsigned)vp[8*SQ] | ((unsigned)vp[9*SQ]<<16);
                    mma_f16(O[j2], a, bfr);
                }
            }
        }
        __syncthreads();
    }
    float inv0 = 1.f/lrow[0], inv1 = 1.f/lrow[1];
    int row0 = m0 + w*16 + g;
    size_t ob0 = (size_t)(b*NT + row0)*ND + h*DH;
    size_t ob1 = (size_t)(b*NT + row0 + 8)*ND + h*DH;
    #pragma unroll
    for(int j2=0;j2<8;j2++){
        int col = j2*8 + q*2;
        *(unsigned*)&g_ctxh[ob0+col] = round_pack(O[j2][0]*inv0, O[j2][1]*inv0);
        *(unsigned*)&g_ctxh[ob1+col] = round_pack(O[j2][2]*inv1, O[j2][3]*inv1);
    }
}

// ================== GEMM kernels (256 threads, 128x128 tiles) ==================

__global__ __launch_bounds__(256,2) void tc_qkv(const float* __restrict__ bias){
    const int m0 = blockIdx.y*128, n0 = blockIdx.x*128;
    float acc[4][4][4] = {};
    core_h(g_lnh + (size_t)m0*ND, ND, nullptr, g_wqkvh + n0, 3*ND, ND, acc);
    const int lane = threadIdx.x&31, w = threadIdx.x>>5;
    const int wm = (w&1)*64, wn = (w>>1)*32;
    const int g = lane>>2, q = lane&3;
    #pragma unroll
    for(int i=0;i<4;i++)
        #pragma unroll
        for(int j=0;j<4;j++)
            #pragma unroll
            for(int hh=0;hh<2;hh++){
                int row = m0 + wm + i*16 + g + hh*8;
                int col = n0 + wn + j*8 + q*2;
                *(unsigned*)&g_qkvh[(size_t)row*3*ND+col] =
                    round_pack(acc[i][j][hh*2] + bias[col], acc[i][j][hh*2+1] + bias[col+1]);
            }
}

__global__ __launch_bounds__(256,2) void tc_o(
    const float* __restrict__ bias, const float* __restrict__ res, float* __restrict__ out){
    const int m0 = blockIdx.y*128, n0 = blockIdx.x*128;
    float acc[4][4][4] = {};
    core_h(g_ctxh + (size_t)m0*ND, ND, nullptr, g_woh + n0, ND, ND, acc);
    const int lane = threadIdx.x&31, w = threadIdx.x>>5;
    const int wm = (w&1)*64, wn = (w>>1)*32;
    const int g = lane>>2, q = lane&3;
    #pragma unroll
    for(int i=0;i<4;i++)
        #pragma unroll
        for(int j=0;j<4;j++)
            #pragma unroll
            for(int hh=0;hh<2;hh++){
                int row = m0 + wm + i*16 + g + hh*8;
                int col = n0 + wn + j*8 + q*2;
                float2 r = *(const float2*)&res[(size_t)row*ND+col];
                float2 o;
                o.x = acc[i][j][hh*2]   + bias[col]   + r.x;
                o.y = acc[i][j][hh*2+1] + bias[col+1] + r.y;
                *(float2*)&out[(size_t)row*ND+col] = o;
            }
}

__global__ __launch_bounds__(256,2) void tc_moe_gemm1(const float* __restrict__ b1){
    const int e = blockIdx.y >> 4;
    const int rt = blockIdx.y & 15;
    if(rt*128 >= g_count[e]) return;
    const int m0 = rt*128, n0 = blockIdx.x*128;
    float acc[4][4][4] = {};
    core_h(g_lnh, ND, &g_slot_token[e*CAP + m0], g_w1h + (size_t)e*ND*NF + n0, NF, ND, acc);
    const int lane = threadIdx.x&31, w = threadIdx.x>>5;
    const int wm = (w&1)*64, wn = (w>>1)*32;
    const int g = lane>>2, q = lane&3;
    #pragma unroll
    for(int i=0;i<4;i++)
        #pragma unroll
        for(int j=0;j<4;j++)
            #pragma unroll
            for(int hh=0;hh<2;hh++){
                int sl  = m0 + wm + i*16 + g + hh*8;
                int col = n0 + wn + j*8 + q*2;
                float v0 = gelu_tanh(acc[i][j][hh*2]   + b1[e*NF + col]);
                float v1 = gelu_tanh(acc[i][j][hh*2+1] + b1[e*NF + col+1]);
                *(unsigned*)&g_hidh[(size_t)(e*CAP+sl)*NF + col] = round_pack(v0, v1);
            }
}

__global__ __launch_bounds__(256,2) void tc_moe_gemm2(const float* __restrict__ b2, float* __restrict__ out){
    const int e = blockIdx.y >> 4;
    const int rt = blockIdx.y & 15;
    const int cnt = g_count[e];
    if(rt*128 >= cnt) return;
    const int m0 = rt*128, n0 = blockIdx.x*128;
    float acc[4][4][4] = {};
    core_h(g_hidh + (size_t)(e*CAP + m0)*NF, NF, nullptr, g_w2h + (size_t)e*NF*ND + n0, ND, NF, acc);
    const int lane = threadIdx.x&31, w = threadIdx.x>>5;
    const int wm = (w&1)*64, wn = (w>>1)*32;
    const int g = lane>>2, q = lane&3;
    #pragma unroll
    for(int i=0;i<4;i++)
        #pragma unroll
        for(int j=0;j<4;j++)
            #pragma unroll
            for(int hh=0;hh<2;hh++){
                int sl = m0 + wm + i*16 + g + hh*8;
                if(sl < cnt){
                    int tok = g_slot_token[e*CAP + sl];
                    float ws = g_slot_w[e*CAP + sl];
                    int col = n0 + wn + j*8 + q*2;
                    atomicAdd(&out[(size_t)tok*ND + col],   ws*(acc[i][j][hh*2]   + b2[e*ND + col]));
                    atomicAdd(&out[(size_t)tok*ND + col+1], ws*(acc[i][j][hh*2+1] + b2[e*ND + col+1]));
                }
            }
}

// ================== auxiliary kernels ==================

__global__ void conv_h_kernel(const float* __restrict__ src, h16* __restrict__ dst){
    size_t i = ((size_t)blockIdx.x*256 + threadIdx.x)*8;
    float4 a = *(const float4*)(src + i);
    float4 b = *(const float4*)(src + i + 4);
    *(uint4*)&dst[i] = make_uint4(round_pack(a.x,a.y), round_pack(a.z,a.w),
                                  round_pack(b.x,b.y), round_pack(b.z,b.w));
}

__global__ void ln_kernel(const float* __restrict__ x,
                          const float* __restrict__ w,
                          const float* __restrict__ b,
                          float* __restrict__ y, h16* __restrict__ yh)
{
    int row = blockIdx.x;
    int t = threadIdx.x;
    float4 v = *(const float4*)(x + (size_t)row*ND + t*4);
    float s = v.x+v.y+v.z+v.w;
    __shared__ float red[256];
    red[t] = s; __syncthreads();
    for(int o=128;o>0;o>>=1){ if(t<o) red[t]+=red[t+o]; __syncthreads(); }
    float mu = red[0]*(1.0f/ND);
    __syncthreads();
    float d0=v.x-mu, d1=v.y-mu, d2=v.z-mu, d3=v.w-mu;
    red[t] = d0*d0+d1*d1+d2*d2+d3*d3; __syncthreads();
    for(int o=128;o>0;o>>=1){ if(t<o) red[t]+=red[t+o]; __syncthreads(); }
    float rstd = rsqrtf(red[0]*(1.0f/ND) + 1e-5f);
    float4 wv = *(const float4*)(w + t*4);
    float4 bv = *(const float4*)(b + t*4);
    float4 o;
    o.x = d0*rstd*wv.x + bv.x;
    o.y = d1*rstd*wv.y + bv.y;
    o.z = d2*rstd*wv.z + bv.z;
    o.w = d3*rstd*wv.w + bv.w;
    *(float4*)(y + (size_t)row*ND + t*4) = o;
    *(uint2*)&yh[(size_t)row*ND + t*4] = make_uint2(round_pack(o.x,o.y), round_pack(o.z,o.w));
}

__global__ void moe_reset_kernel()
{
    int i = blockIdx.x*256 + threadIdx.x;
    if(i < NSLOT) g_slot_token[i] = -1;
    if(i < NE) g_count[i] = 0;
}

__global__ void gate_kernel(const float* __restrict__ wg)
{
    int token = blockIdx.x*8 + (threadIdx.x>>5);
    int lane = threadIdx.x & 31;
    const float* t = g_ln + (size_t)token*ND;
    float acc[NE] = {};
    for(int d=lane; d<ND; d+=32){
        float td = t[d];
        const float* w = wg + d*NE;
        #pragma unroll
        for(int e=0;e<NE;e++) acc[e] += td*w[e];
    }
    #pragma unroll
    for(int e=0;e<NE;e++)
        #pragma unroll
        for(int o=16;o>0;o>>=1) acc[e] += __shfl_xor_sync(0xffffffffu, acc[e], o);
    if(lane==0){
        float mx = -1e30f;
        #pragma unroll
        for(int e=0;e<NE;e++) mx = fmaxf(mx, acc[e]);
        float p[NE], s=0.f;
        #pragma unroll
        for(int e=0;e<NE;e++){ p[e] = expf(acc[e]-mx); s += p[e]; }
        float inv = 1.0f/s;
        #pragma unroll
        for(int e=0;e<NE;e++) p[e] *= inv;
        int e0 = 0;
        #pragma unroll
        for(int e=1;e<NE;e++) if(p[e] > p[e0]) e0 = e;
        int e1 = (e0==0) ? 1 : 0;
        #pragma unroll
        for(int e=0;e<NE;e++) if(e!=e0 && p[e] > p[e1]) e1 = e;
        float w0 = p[e0], w1 = p[e1];
        float rn = 1.0f/(w0+w1);
        w0 *= rn; w1 *= rn;
        int p0 = atomicAdd(&g_count[e0], 1);
        g_slot_token[e0*CAP + p0] = token; g_slot_w[e0*CAP + p0] = w0;
        int p1 = atomicAdd(&g_count[e1], 1);
        g_slot_token[e1*CAP + p1] = token; g_slot_w[e1*CAP + p1] = w1;
    }
}

// ================== launch ==================
extern "C" void kernel_launch(void* const* d_in, const int* in_sizes, int n_in,
                              void* d_out, int out_size)
{
    const float* x    = (const float*)d_in[0];
    const float* ln1w = (const float*)d_in[1];
    const float* ln1b = (const float*)d_in[2];
    const float* ln2w = (const float*)d_in[3];
    const float* ln2b = (const float*)d_in[4];
    const float* wqkv = (const float*)d_in[5];
    const float* bqkv = (const float*)d_in[6];
    const float* wo   = (const float*)d_in[7];
    const float* bo   = (const float*)d_in[8];
    const float* wg   = (const float*)d_in[9];
    const float* w1   = (const float*)d_in[10];
    const float* b1   = (const float*)d_in[11];
    const float* w2   = (const float*)d_in[12];
    const float* b2   = (const float*)d_in[13];
    float* out = (float*)d_out;

    float *p_ln;
    h16 *p_lnh, *p_wqkvh, *p_woh, *p_w1h, *p_w2h;
    cudaGetSymbolAddress((void**)&p_ln,    g_ln);
    cudaGetSymbolAddress((void**)&p_lnh,   g_lnh);
    cudaGetSymbolAddress((void**)&p_wqkvh, g_wqkvh);
    cudaGetSymbolAddress((void**)&p_woh,   g_woh);
    cudaGetSymbolAddress((void**)&p_w1h,   g_w1h);
    cudaGetSymbolAddress((void**)&p_w2h,   g_w2h);

    cudaFuncSetAttribute(flash_attn,   cudaFuncAttributeMaxDynamicSharedMemorySize, FLASH_SMEM);
    cudaFuncSetAttribute(tc_qkv,       cudaFuncAttributeMaxDynamicSharedMemorySize, GEMM_SMEM);
    cudaFuncSetAttribute(tc_o,         cudaFuncAttributeMaxDynamicSharedMemorySize, GEMM_SMEM);
    cudaFuncSetAttribute(tc_moe_gemm1, cudaFuncAttributeMaxDynamicSharedMemorySize, GEMM_SMEM);
    cudaFuncSetAttribute(tc_moe_gemm2, cudaFuncAttributeMaxDynamicSharedMemorySize, GEMM_SMEM);

    // Side stream: all weight conversions + MoE routing reset (no deps).
    cudaStream_t s2;
    cudaEvent_t evFork, evJoin, evReset;
    cudaStreamCreateWithFlags(&s2, cudaStreamNonBlocking);
    cudaEventCreateWithFlags(&evFork,  cudaEventDisableTiming);
    cudaEventCreateWithFlags(&evJoin,  cudaEventDisableTiming);
    cudaEventCreateWithFlags(&evReset, cudaEventDisableTiming);

    // main stream: qkv weight conv (needed immediately)
    conv_h_kernel<<<3*ND*ND/2048, 256>>>(wqkv, p_wqkvh);

    // fork side stream
    cudaEventRecord(evFork, 0);
    cudaStreamWaitEvent(s2, evFork, 0);
    moe_reset_kernel<<<NSLOT/256, 256, 0, s2>>>();
    cudaEventRecord(evReset, s2);
    conv_h_kernel<<<ND*ND/2048,   256, 0, s2>>>(wo, p_woh);
    conv_h_kernel<<<NE*ND*NF/2048,256, 0, s2>>>(w1, p_w1h);
    conv_h_kernel<<<NE*NF*ND/2048,256, 0, s2>>>(w2, p_w2h);
    cudaEventRecord(evJoin, s2);

    // main stream: attention phase (overlaps with side-stream convs)
    ln_kernel<<<NTOK, 256>>>(x, ln1w, ln1b, p_ln, p_lnh);
    tc_qkv<<<dim3(3*ND/128, NTOK/128), 256, GEMM_SMEM>>>(bqkv);
    flash_attn<<<dim3(NT/128, NB*NHEAD), 256, FLASH_SMEM>>>();

    // join: wo/w1/w2 fp16 must be ready before tc_o and MoE
    cudaStreamWaitEvent(0, evJoin, 0);

    tc_o<<<dim3(ND/128, NTOK/128), 256, GEMM_SMEM>>>(bo, x, out);
    ln_kernel<<<NTOK, 256>>>(out, ln2w, ln2b, p_ln, p_lnh);
    cudaStreamWaitEvent(0, evReset, 0);
    gate_kernel<<<NTOK/8, 256>>>(wg);
    tc_moe_gemm1<<<dim3(NF/128, NE*16), 256, GEMM_SMEM>>>(b1);
    tc_moe_gemm2<<<dim3(ND/128, NE*16), 256, GEMM_SMEM>>>(b2, out);

    cudaStreamDestroy(s2);
    cudaEventDestroy(evFork);
    cudaEventDestroy(evJoin);
    cudaEventDestroy(evReset);
}